// round 16
// baseline (speedup 1.0000x reference)
#include <cuda_runtime.h>
#include <cuda_fp16.h>
#include <cstdint>

// Problem dims
constexpr int NB = 256, NT = 512, NF = 256, NH = 1024, NG = 4096;
constexpr int NKD = NH + NF; // 1280
constexpr int NOUT = 64;

// Weight-stationary persistent tiling: BM=128, BN=64, BK=64.
// B (weights) resident in smem all 512 steps; only A (h/x) streamed.
constexpr int BM = 128, BN = 64, BK = 64;
constexpr int NKT = NKD / BK;   // 20 (kt 0..15 = h blocks, 16..19 = x blocks)
constexpr int NST = 4;
constexpr int A_BY = BM * BK * 2;        // 16384 B / stage
constexpr int A_ST_H = A_BY / 2;         // 8192 halves
constexpr int B_SM_H = NKT * BN * BK;    // 81920 halves (163840 B)
constexpr int SMEM_BYTES = NST * A_BY + B_SM_H * 2; // 229376
constexpr int NCTAS = (NG / BN) * (NB / BM);        // 128
constexpr int HSZ = 16 * NB * BK;        // 262144 halves per h buffer

// per-16 k permutation: position q holds k = PERM[q]
__device__ __constant__ int c_perm[16] = {0,1,8,9, 2,3,10,11, 4,5,12,13, 6,7,14,15};
__device__ __constant__ int c_pinv[16] = {0,1,4,5, 8,9,12,13, 2,3,6,7, 10,11,14,15};

// ---------------- device scratch ----------------
__device__ __half g_MB[(long)NKT * NG * BK];     // [kt(20)][n][64] weights
__device__ __half g_xB[(long)NT * 4 * NB * BK];  // [t][kb(4)][b][64] fp16 x blocks
__device__ __half g_h[2 * HSZ];                  // ping-pong hidden, [kb(16)][b][64]
__device__ float  g_bI[NG];
__device__ float  g_MLP[2048 * NH];
__device__ float  g_cf[NB * NH];
__device__ float  g_hf[NB * NH];
__device__ float  g_y1[NB * NH];
__device__ unsigned g_maskw[NB * 16];
__device__ unsigned g_hcnt[32];                  // [buf][kb(16)] ready counters

// ---------------- helpers ----------------
__device__ __forceinline__ unsigned smem_u32(const void* p) {
    unsigned a;
    asm("{ .reg .u64 t; cvta.to.shared.u64 t, %1; cvt.u32.u64 %0, t; }" : "=r"(a) : "l"(p));
    return a;
}
__device__ __forceinline__ float fex2(float x) {
    float y; asm("ex2.approx.f32 %0, %1;" : "=f"(y) : "f"(x)); return y;
}
__device__ __forceinline__ float frcp(float x) {
    float y; asm("rcp.approx.f32 %0, %1;" : "=f"(y) : "f"(x)); return y;
}
__device__ __forceinline__ float sigmf(float x) {
    return frcp(1.0f + fex2(-1.4426950408889634f * x));
}
__device__ __forceinline__ float tanhfa(float x) {
    return 1.0f - 2.0f * frcp(1.0f + fex2(2.8853900817779268f * x));
}
__device__ __forceinline__ void mma16(float* d, unsigned a0, unsigned a1, unsigned a2,
                                      unsigned a3, unsigned b0, unsigned b1) {
    asm volatile(
        "mma.sync.aligned.m16n8k16.row.col.f32.f16.f16.f32 "
        "{%0,%1,%2,%3}, {%4,%5,%6,%7}, {%8,%9}, {%0,%1,%2,%3};"
        : "+f"(d[0]), "+f"(d[1]), "+f"(d[2]), "+f"(d[3])
        : "r"(a0), "r"(a1), "r"(a2), "r"(a3), "r"(b0), "r"(b1));
}
__device__ __forceinline__ void mbar_init(unsigned mbar, unsigned cnt) {
    asm volatile("mbarrier.init.shared.b64 [%0], %1;" :: "r"(mbar), "r"(cnt) : "memory");
}
__device__ __forceinline__ void mbar_inval(unsigned mbar) {
    asm volatile("mbarrier.inval.shared.b64 [%0];" :: "r"(mbar) : "memory");
}
__device__ __forceinline__ void mbar_expect_tx(unsigned mbar, unsigned bytes) {
    asm volatile("mbarrier.arrive.expect_tx.shared.b64 _, [%0], %1;"
                 :: "r"(mbar), "r"(bytes) : "memory");
}
__device__ __forceinline__ void mbar_wait(unsigned mbar, unsigned parity) {
    asm volatile(
        "{\n\t.reg .pred P;\n"
        "W%=:\n\t"
        "mbarrier.try_wait.parity.acquire.cta.shared::cta.b64 P, [%0], %1, 0x989680;\n\t"
        "@!P bra W%=;\n\t}"
        :: "r"(mbar), "r"(parity) : "memory");
}
__device__ __forceinline__ void bulk_g2s(unsigned dst, const void* src, unsigned bytes,
                                         unsigned mbar) {
    asm volatile(
        "cp.async.bulk.shared::cta.global.mbarrier::complete_tx::bytes [%0], [%1], %2, [%3];"
        :: "r"(dst), "l"(src), "r"(bytes), "r"(mbar) : "memory");
}
__device__ __forceinline__ void wait_cnt(const unsigned* p, unsigned target) {
    unsigned v;
    do {
        asm volatile("ld.acquire.gpu.u32 %0, [%1];" : "=r"(v) : "l"(p) : "memory");
    } while (v < target);
}

// ---------------- mask (bit-packed; atomicOr idempotent across replays) ----
__global__ void __launch_bounds__(256) mask_kernel(const float* __restrict__ x) {
    int warp = (blockIdx.x * 256 + threadIdx.x) >> 5;
    int lane = threadIdx.x & 31;
    if (warp >= NB * NT) return;
    int b = warp >> 9, t = warp & 511;
    const float4* p = (const float4*)(x + (long)warp * NF);
    float4 v1 = p[lane];
    float4 v2 = p[lane + 32];
    bool nz = v1.x != 0.f || v1.y != 0.f || v1.z != 0.f || v1.w != 0.f ||
              v2.x != 0.f || v2.y != 0.f || v2.z != 0.f || v2.w != 0.f;
    unsigned m = __ballot_sync(0xffffffffu, nz);
    if (lane == 0 && m != 0u)
        atomicOr(&g_maskw[b * 16 + (t >> 5)], 1u << (t & 31));
}

// ---------------- prep: weights [kt][n][64], swizzle key n&3, per-16 perm --------
__global__ void __launch_bounds__(256) prep_weights(
    const float* __restrict__ W, const float* __restrict__ U, const float* __restrict__ b) {
    long idx = (long)blockIdx.x * 256 + threadIdx.x; // 20*NG*64 = 5242880
    int hs = (int)(idx & 63);
    int n = (int)((idx >> 6) & (NG - 1));
    int kt = (int)(idx >> 18);
    int cc = (hs >> 4) ^ (n & 3);
    int hc = (cc << 4) | (hs & 15);
    int kl = (hc & ~15) | c_perm[hc & 15];
    int k = kt * BK + kl;
    int gate = n & 3, j = n >> 2;
    float v = (k < NH) ? U[(long)k * NG + gate * NH + j]
                       : W[(long)(k - NH) * NG + gate * NH + j];
    g_MB[idx] = __float2half_rn(v);
    if (hs == 0 && kt == 0) g_bI[n] = b[gate * NH + j];
}

// ---------------- prep: x blocks + MLP combine + h0 zero + counter reset --------
__global__ void __launch_bounds__(256) prep_misc(
    const float* __restrict__ x, const float* __restrict__ W1) {
    const long N0 = (long)NT * 4 * NB * 4;  // x chunks of 16 halves (4 per 64-row)
    const long N1 = (long)2048 * NH;
    const long N2 = (long)HSZ / 8;          // h0 zero in uint4 units
    long idx = (long)blockIdx.x * 256 + threadIdx.x;
    if (idx < N0) {
        int cs = (int)(idx & 3);
        int bb = (int)((idx >> 2) & 255);
        int kb = (int)((idx >> 10) & 3);
        int t = (int)(idx >> 12);
        int cc = cs ^ (bb & 3);
        const float* src = x + ((long)bb * NT + t) * NF + kb * 64 + cc * 16;
        float4 v0 = *(const float4*)(src);
        float4 v1 = *(const float4*)(src + 4);
        float4 v2 = *(const float4*)(src + 8);
        float4 v3 = *(const float4*)(src + 12);
        __half2 h[8];
        h[0] = __floats2half2_rn(v0.x, v0.y);
        h[1] = __floats2half2_rn(v2.x, v2.y);
        h[2] = __floats2half2_rn(v0.z, v0.w);
        h[3] = __floats2half2_rn(v2.z, v2.w);
        h[4] = __floats2half2_rn(v1.x, v1.y);
        h[5] = __floats2half2_rn(v3.x, v3.y);
        h[6] = __floats2half2_rn(v1.z, v1.w);
        h[7] = __floats2half2_rn(v3.z, v3.w);
        __half* dst = g_xB + ((((long)t * 4 + kb) * NB + bb) * 64 + cs * 16);
        *(uint4*)(dst) = *(uint4*)(h);
        *(uint4*)(dst + 8) = *(uint4*)(h + 4);
    } else if (idx < N0 + N1) {
        long r = idx - N0;
        int k = (int)(r >> 10), m = (int)(r & (NH - 1));
        float v = (k < NH) ? (W1[(long)k * NH + m] + W1[(long)(k + NH) * NH + m])
                           : W1[(long)(k + NH) * NH + m];
        g_MLP[r] = v;
    } else if (idx < N0 + N1 + N2) {
        ((uint4*)g_h)[idx - N0 - N1] = make_uint4(0, 0, 0, 0);
    } else if (idx < N0 + N1 + N2 + 32) {
        g_hcnt[idx - N0 - N1 - N2] = 0;
    }
}

// ---------------- persistent LSTM recurrence (weight-stationary) -----------------
__global__ void __launch_bounds__(256) lstm_persistent() {
    extern __shared__ __align__(128) char dsm[];
    __half* sh = (__half*)dsm;                     // A stages: 4 x 8192 halves
    __half* Bp = sh + NST * A_ST_H;                // persistent B: 81920 halves
    __shared__ __align__(8) unsigned long long s_mbar[NST];

    const int tid = threadIdx.x;
    const int lane = tid & 31;
    const int w = tid >> 5;
    const int wm = w & 3;       // 4 m-tiles of 32 rows
    const int wn = w >> 2;      // 2 n-tiles of 32 cols
    const int bn = blockIdx.x * BN;
    const int bm = blockIdx.y * BM;
    const int g = lane >> 2;
    const int c = lane & 3;
    const int c4 = 4 * c;
    const int odd = c & 1;
    const int g3 = g & 3;
    const int kb_own = bn >> 8;     // the single 64-unit h block this CTA writes

    const unsigned smb = smem_u32(sh);
    const unsigned mbb = smem_u32(s_mbar);

    if (tid == 0)
        for (int s = 0; s < NST; ++s) mbar_init(mbb + 8 * s, 1);
    __syncthreads();

    // one-time persistent weight load: 20 blocks x 8 KB (512 uint4 each)
    for (int kt = 0; kt < NKT; ++kt) {
        const uint4* src = (const uint4*)(g_MB + ((long)kt * NG + bn) * BK);
        uint4* dst = (uint4*)(Bp + kt * (BN * BK));
        dst[tid] = src[tid];
        dst[tid + 256] = src[tid + 256];
    }

    // fragment identities (t-independent)
    const int bgA = bm + wm * 32 + g + (odd ? 8 : 0);
    const int bgB = bgA + 16;
    int jj[4], hposA[4], hposB[4];
    float4 b4[4];
#pragma unroll
    for (int nt = 0; nt < 4; ++nt) {
        int j = (bn >> 2) + wn * 8 + nt * 2 + (c >> 1);
        jj[nt] = j;
        int q = (j & ~15) | c_pinv[j & 15];
        int kb = q >> 6, hc = q & 63;
        hposA[nt] = ((kb * NB + bgA) << 6) + (((hc >> 4) ^ (bgA & 3)) << 4) + (hc & 15);
        hposB[nt] = ((kb * NB + bgB) << 6) + (((hc >> 4) ^ (bgB & 3)) << 4) + (hc & 15);
        b4[nt] = *(const float4*)(g_bI + 4 * j);
    }
    float cst[8], hst[8];
#pragma unroll
    for (int i = 0; i < 8; ++i) { cst[i] = 0.0f; hst[i] = 0.0f; }

    int ph[NST] = {0, 0, 0, 0};
    unsigned mw0 = 0, mw1 = 0;

    __syncthreads();  // B resident + mbars initialized

    // A fill for process index p (p 0..3 -> x blocks kt16..19; 4..19 -> h kt0..15)
    auto fill_p = [&](int p, int t, const __half* hsrc, int srcbuf, unsigned target) {
        const int kt = (p < 4) ? 16 + p : p - 4;
        const int s = p & 3;
        mbar_expect_tx(mbb + 8 * s, (unsigned)A_BY);
        if (kt < 16) {
            if (t > 0) wait_cnt(&g_hcnt[srcbuf * 16 + kt], target);
            bulk_g2s(smb + s * A_BY, hsrc + ((long)kt * NB + bm) * BK, A_BY, mbb + 8 * s);
        } else {
            bulk_g2s(smb + s * A_BY,
                     g_xB + (((long)t * 4 + (kt - 16)) * NB + bm) * BK, A_BY, mbb + 8 * s);
        }
    };

    // prologue: fills p=0,1 of t=0 (x blocks, ungated)
    if (tid == 0) {
        mbar_expect_tx(mbb + 0, (unsigned)A_BY);
        bulk_g2s(smb + 0, g_xB + ((long)0 * NB + bm) * BK, A_BY, mbb + 0);
        mbar_expect_tx(mbb + 8, (unsigned)A_BY);
        bulk_g2s(smb + A_BY, g_xB + ((long)1 * NB + bm) * BK, A_BY, mbb + 8);
    }

    for (int t = 0; t < NT; ++t) {
        const int srcbuf = t & 1;
        const __half* __restrict__ hsrc = g_h + srcbuf * HSZ;
        __half* __restrict__ hdst = g_h + (srcbuf ^ 1) * HSZ;
        const unsigned target = 8u * (unsigned)((t + 1) >> 1);

        if ((t & 31) == 0) {
            mw0 = g_maskw[bgA * 16 + (t >> 5)];
            mw1 = g_maskw[bgB * 16 + (t >> 5)];
        }

        float acc[2][4][4];
#pragma unroll
        for (int i = 0; i < 2; ++i)
#pragma unroll
            for (int j = 0; j < 4; ++j)
#pragma unroll
                for (int k = 0; k < 4; ++k) acc[i][j][k] = 0.0f;

        for (int p = 0; p < NKT; ++p) {
            const int s = p & 3;
            const int kt = (p < 4) ? 16 + p : p - 4;
            if ((p & 1) == 0) {
                // even p: w0 waits, CTA sync (all past p-1), then fills p+2,p+3
                // (reusing stages of fills p-2,p-1 -> consumed). p==18: next x.
                if (w == 0) mbar_wait(mbb + 8 * s, (unsigned)ph[s]);
                __syncthreads();
                if (tid == 0) {
                    if (p == 0 && t > 0) {  // publish t-1's h (stores covered by sync)
                        __threadfence();
                        atomicAdd(&g_hcnt[srcbuf * 16 + kb_own], 1u);
                    }
                    if (p <= 16) {
                        fill_p(p + 2, t, hsrc, srcbuf, target);
                        fill_p(p + 3, t, hsrc, srcbuf, target);
                    } else if (t + 1 < NT) {  // p == 18
                        mbar_expect_tx(mbb + 0, (unsigned)A_BY);
                        bulk_g2s(smb + 0,
                                 g_xB + (((long)(t + 1) * 4 + 0) * NB + bm) * BK,
                                 A_BY, mbb + 0);
                        mbar_expect_tx(mbb + 8, (unsigned)A_BY);
                        bulk_g2s(smb + A_BY,
                                 g_xB + (((long)(t + 1) * 4 + 1) * NB + bm) * BK,
                                 A_BY, mbb + 8);
                    }
                }
            } else {
                mbar_wait(mbb + 8 * s, (unsigned)ph[s]);
            }
            ph[s] ^= 1;

            const __half* arow = sh + s * A_ST_H + (wm * 32 + g) * BK;
            const __half* brow = Bp + kt * (BN * BK) + (wn * 32 + g) * BK;

            // double-buffered fragment pipeline over the 4 chunks
            uint2 fA[2][4], fB[2][4];
            {
                const int o = (g3 << 4) + c4;  // ch 0
                fA[0][0] = *(const uint2*)(arow + o);
                fA[0][1] = *(const uint2*)(arow + 512 + o);
                fA[0][2] = *(const uint2*)(arow + 1024 + o);
                fA[0][3] = *(const uint2*)(arow + 1536 + o);
                fB[0][0] = *(const uint2*)(brow + o);
                fB[0][1] = *(const uint2*)(brow + 512 + o);
                fB[0][2] = *(const uint2*)(brow + 1024 + o);
                fB[0][3] = *(const uint2*)(brow + 1536 + o);
            }
#pragma unroll
            for (int ch = 0; ch < 4; ++ch) {
                const int cb = ch & 1;
                if (ch < 3) {
                    const int o = (((ch + 1) ^ g3) << 4) + c4;
                    uint2* a = fA[cb ^ 1];
                    uint2* b = fB[cb ^ 1];
                    a[0] = *(const uint2*)(arow + o);
                    a[1] = *(const uint2*)(arow + 512 + o);
                    a[2] = *(const uint2*)(arow + 1024 + o);
                    a[3] = *(const uint2*)(arow + 1536 + o);
                    b[0] = *(const uint2*)(brow + o);
                    b[1] = *(const uint2*)(brow + 512 + o);
                    b[2] = *(const uint2*)(brow + 1024 + o);
                    b[3] = *(const uint2*)(brow + 1536 + o);
                }
                const uint2* a = fA[cb];
                const uint2* b = fB[cb];
                mma16(acc[0][0], a[0].x, a[1].x, a[0].y, a[1].y, b[0].x, b[0].y);
                mma16(acc[0][1], a[0].x, a[1].x, a[0].y, a[1].y, b[1].x, b[1].y);
                mma16(acc[0][2], a[0].x, a[1].x, a[0].y, a[1].y, b[2].x, b[2].y);
                mma16(acc[0][3], a[0].x, a[1].x, a[0].y, a[1].y, b[3].x, b[3].y);
                mma16(acc[1][0], a[2].x, a[3].x, a[2].y, a[3].y, b[0].x, b[0].y);
                mma16(acc[1][1], a[2].x, a[3].x, a[2].y, a[3].y, b[1].x, b[1].y);
                mma16(acc[1][2], a[2].x, a[3].x, a[2].y, a[3].y, b[2].x, b[2].y);
                mma16(acc[1][3], a[2].x, a[3].x, a[2].y, a[3].y, b[3].x, b[3].y);
            }
        }

        // register-state epilogue (shuffle gate quads); no trailing CTA sync —
        // the next step's p=0 sync covers the h stores before the publish.
        const unsigned bit0 = (mw0 >> (t & 31)) & 1u;
        const unsigned bit1 = (mw1 >> (t & 31)) & 1u;
#pragma unroll
        for (int i = 0; i < 8; ++i) {
            const int mt = i >> 2, nt = i & 3;
            float v0 = acc[mt][nt][0], v1 = acc[mt][nt][1];
            float v2 = acc[mt][nt][2], v3 = acc[mt][nt][3];
            float sx = odd ? v0 : v2;
            float sy = odd ? v1 : v3;
            float gx = __shfl_xor_sync(0xffffffffu, sx, 1);
            float gy = __shfl_xor_sync(0xffffffffu, sy, 1);
            float zi, zf, zg, zo;
            if (!odd) { zi = v0; zf = v1; zg = gx; zo = gy; }
            else      { zi = gx; zf = gy; zg = v2; zo = v3; }
            float4 bb = b4[nt];
            zi += bb.x; zf += bb.y; zg += bb.z; zo += bb.w;
            float iv = sigmf(zi), fv = sigmf(zf), gv = tanhfa(zg), ov = sigmf(zo);
            float cn = fv * cst[i] + iv * gv;
            float hn = ov * tanhfa(cn);
            unsigned msk = mt ? bit1 : bit0;
            if (!msk) { cn = cst[i]; hn = hst[i]; }
            cst[i] = cn;
            hst[i] = hn;
            hdst[mt ? hposB[nt] : hposA[nt]] = __float2half_rn(hn);
        }
    }

    // final c (fp32) for the MLP head
#pragma unroll
    for (int i = 0; i < 8; ++i) {
        int bg = (i >> 2) ? bgB : bgA;
        g_cf[(long)bg * NH + jj[i & 3]] = cst[i];
    }
    __syncthreads();
    if (tid == 0)
        for (int s = 0; s < NST; ++s) mbar_inval(mbb + 8 * s);
}

// un-permute/un-swizzle final h (buffer 0 after 512 steps) to fp32
__global__ void __launch_bounds__(256) unperm_h() {
    int idx = blockIdx.x * 256 + threadIdx.x; // NB*NH
    int b = idx >> 10, j = idx & 1023;
    int q = (j & ~15) | c_pinv[j & 15];
    int kb = q >> 6, hc = q & 63;
    long off = (((long)kb * NB + b) << 6) + (((hc >> 4) ^ (b & 3)) << 4) + (hc & 15);
    g_hf[idx] = __half2float(g_h[off]);
}

// ---------------- MLP head ----------------
__global__ void __launch_bounds__(256) mlp1_kernel(const float* __restrict__ b1) {
    __shared__ float a_s[64 * 20];
    __shared__ float b_s[16 * 68];
    int tid = threadIdx.x;
    int bn = blockIdx.x * 64, bm = blockIdx.y * 64;
    int ty = tid >> 4, tx = tid & 15;
    float acc[4][4];
#pragma unroll
    for (int i = 0; i < 4; ++i)
#pragma unroll
        for (int j = 0; j < 4; ++j) acc[i][j] = 0.0f;

    for (int kt = 0; kt < 128; ++kt) {
        int k0 = kt * 16;
        {
            int m = tid >> 2, kq = tid & 3;
            int k = k0 + 4 * kq;
            const float* src = (k < NH) ? (g_hf + (long)(bm + m) * NH + k)
                                        : (g_cf + (long)(bm + m) * NH + (k - NH));
            *(float4*)(a_s + m * 20 + 4 * kq) = *(const float4*)src;
        }
        {
            int kr = tid >> 4, cq = tid & 15;
            *(float4*)(b_s + kr * 68 + 4 * cq) =
                *(const float4*)(g_MLP + (long)(k0 + kr) * NH + bn + 4 * cq);
        }
        __syncthreads();
#pragma unroll
        for (int k = 0; k < 16; ++k) {
            float ar[4], br[4];
#pragma unroll
            for (int i = 0; i < 4; ++i) {
                ar[i] = a_s[(4 * ty + i) * 20 + k];
                br[i] = b_s[k * 68 + 4 * tx + i];
            }
#pragma unroll
            for (int i = 0; i < 4; ++i)
#pragma unroll
                for (int j = 0; j < 4; ++j) acc[i][j] += ar[i] * br[j];
        }
        __syncthreads();
    }
#pragma unroll
    for (int i = 0; i < 4; ++i)
#pragma unroll
        for (int j = 0; j < 4; ++j) {
            float v = acc[i][j] + b1[bn + 4 * tx + j];
            v = v > 0.0f ? v : 0.2f * v;
            g_y1[(long)(bm + 4 * ty + i) * NH + bn + 4 * tx + j] = v;
        }
}

__global__ void __launch_bounds__(64) mlp2_kernel(
    const float* __restrict__ W2, const float* __restrict__ b2, float* __restrict__ out) {
    __shared__ float row[NH];
    int bg = blockIdx.x;
    int o = threadIdx.x;
    for (int i = o; i < NH; i += 64) row[i] = g_y1[(long)bg * NH + i];
    __syncthreads();
    float acc = b2[o];
#pragma unroll 8
    for (int k = 0; k < NH; ++k) acc += row[k] * W2[(long)k * NOUT + o];
    out[(long)bg * NOUT + o] = acc;
}

// ---------------- launch ----------------
extern "C" void kernel_launch(void* const* d_in, const int* in_sizes, int n_in,
                              void* d_out, int out_size) {
    const float* x  = (const float*)d_in[0];
    const float* W  = (const float*)d_in[1];
    const float* U  = (const float*)d_in[2];
    const float* b  = (const float*)d_in[3];
    const float* W1 = (const float*)d_in[4];
    const float* b1 = (const float*)d_in[5];
    const float* W2 = (const float*)d_in[6];
    const float* b2 = (const float*)d_in[7];
    float* out = (float*)d_out;

    cudaFuncSetAttribute(lstm_persistent,
                         cudaFuncAttributeMaxDynamicSharedMemorySize, SMEM_BYTES);

    const long WN = (long)NKT * NG * BK;  // 5242880
    const long MN = (long)NT * 4 * NB * 4 + (long)2048 * NH + (long)HSZ / 8 + 32;

    // lstm_persistent is the 4th launch (ncu profiles launch index 3)
    mask_kernel<<<(NB * NT * 32) / 256, 256>>>(x);
    prep_weights<<<(int)(WN / 256), 256>>>(W, U, b);
    prep_misc<<<(int)((MN + 255) / 256), 256>>>(x, W1);
    lstm_persistent<<<dim3(NG / BN, NB / BM), 256, SMEM_BYTES>>>();
    unperm_h<<<(NB * NH) / 256, 256>>>();
    mlp1_kernel<<<dim3(NH / 64, NB / 64), 256>>>(b1);
    mlp2_kernel<<<NB, 64>>>(W2, b2, out);
}

// round 17
// speedup vs baseline: 1.3419x; 1.3419x over previous
#include <cuda_runtime.h>
#include <cuda_fp16.h>
#include <cstdint>

// Problem dims
constexpr int NB = 256, NT = 512, NF = 256, NH = 1024, NG = 4096;
constexpr int NKD = NH + NF; // 1280
constexpr int NOUT = 64;

// Persistent step-GEMM tiling (fp16 mma.sync + cp.async.bulk, 4-stage, frag-DB,
// half-syncs, x-first, gate-aware column mapping -> shuffle-free epilogue)
constexpr int BM = 64, BN = 128, BK = 128;
constexpr int NKT = NKD / BK;   // 10
constexpr int NST = 4;
constexpr int A_BY = BM * BK * 2;        // 16384 B
constexpr int B_BY = BN * BK * 2;        // 32768 B
constexpr int ST_BY = A_BY + B_BY;       // 49152 B
constexpr int ST_H = ST_BY / 2;
constexpr int A_H = A_BY / 2;
constexpr int SMEM_BYTES = NST * ST_BY;  // 196608
constexpr int NCTAS = (NB / BM) * (NG / BN); // 128
constexpr int HSZ = 8 * NB * BK;         // halves per h buffer

// per-16 k permutation: position q holds k = PERM[q]
__device__ __constant__ int c_perm[16] = {0,1,8,9, 2,3,10,11, 4,5,12,13, 6,7,14,15};
__device__ __constant__ int c_pinv[16] = {0,1,4,5, 8,9,12,13, 2,3,6,7, 10,11,14,15};

// ---------------- device scratch ----------------
__device__ __half g_MB[(long)10 * NG * BK];      // [kt(10)][n][128] weights
__device__ __half g_xB[(long)NT * 2 * NB * BK];  // [t][kb][b][128] fp16 x blocks
__device__ __half g_h[2 * HSZ];                  // ping-pong hidden, block layout
__device__ float  g_bI[NG];                      // bias, unit-major [4u+gate]
__device__ float  g_MLP[2048 * NH];
__device__ float  g_cf[NB * NH];
__device__ float  g_hf[NB * NH];
__device__ float  g_y1[NB * NH];
__device__ unsigned g_maskw[NB * 16];
__device__ unsigned g_hcnt[16];                  // [buf][kb(8)] ready counters

// ---------------- helpers ----------------
__device__ __forceinline__ unsigned smem_u32(const void* p) {
    unsigned a;
    asm("{ .reg .u64 t; cvta.to.shared.u64 t, %1; cvt.u32.u64 %0, t; }" : "=r"(a) : "l"(p));
    return a;
}
__device__ __forceinline__ float fex2(float x) {
    float y; asm("ex2.approx.f32 %0, %1;" : "=f"(y) : "f"(x)); return y;
}
__device__ __forceinline__ float frcp(float x) {
    float y; asm("rcp.approx.f32 %0, %1;" : "=f"(y) : "f"(x)); return y;
}
__device__ __forceinline__ float sigmf(float x) {
    return frcp(1.0f + fex2(-1.4426950408889634f * x));
}
__device__ __forceinline__ float tanhfa(float x) {
    return 1.0f - 2.0f * frcp(1.0f + fex2(2.8853900817779268f * x));
}
__device__ __forceinline__ void mma16(float* d, unsigned a0, unsigned a1, unsigned a2,
                                      unsigned a3, unsigned b0, unsigned b1) {
    asm volatile(
        "mma.sync.aligned.m16n8k16.row.col.f32.f16.f16.f32 "
        "{%0,%1,%2,%3}, {%4,%5,%6,%7}, {%8,%9}, {%0,%1,%2,%3};"
        : "+f"(d[0]), "+f"(d[1]), "+f"(d[2]), "+f"(d[3])
        : "r"(a0), "r"(a1), "r"(a2), "r"(a3), "r"(b0), "r"(b1));
}
__device__ __forceinline__ void mbar_init(unsigned mbar, unsigned cnt) {
    asm volatile("mbarrier.init.shared.b64 [%0], %1;" :: "r"(mbar), "r"(cnt) : "memory");
}
__device__ __forceinline__ void mbar_inval(unsigned mbar) {
    asm volatile("mbarrier.inval.shared.b64 [%0];" :: "r"(mbar) : "memory");
}
__device__ __forceinline__ void mbar_expect_tx(unsigned mbar, unsigned bytes) {
    asm volatile("mbarrier.arrive.expect_tx.shared.b64 _, [%0], %1;"
                 :: "r"(mbar), "r"(bytes) : "memory");
}
__device__ __forceinline__ void mbar_wait(unsigned mbar, unsigned parity) {
    asm volatile(
        "{\n\t.reg .pred P;\n"
        "W%=:\n\t"
        "mbarrier.try_wait.parity.acquire.cta.shared::cta.b64 P, [%0], %1, 0x989680;\n\t"
        "@!P bra W%=;\n\t}"
        :: "r"(mbar), "r"(parity) : "memory");
}
__device__ __forceinline__ void bulk_g2s(unsigned dst, const void* src, unsigned bytes,
                                         unsigned mbar) {
    asm volatile(
        "cp.async.bulk.shared::cta.global.mbarrier::complete_tx::bytes [%0], [%1], %2, [%3];"
        :: "r"(dst), "l"(src), "r"(bytes), "r"(mbar) : "memory");
}
__device__ __forceinline__ void wait_cnt(const unsigned* p, unsigned target) {
    unsigned v;
    do {
        asm volatile("ld.acquire.gpu.u32 %0, [%1];" : "=r"(v) : "l"(p) : "memory");
    } while (v < target);
}

// ---------------- mask (bit-packed; atomicOr idempotent across replays) ----
__global__ void __launch_bounds__(256) mask_kernel(const float* __restrict__ x) {
    int warp = (blockIdx.x * 256 + threadIdx.x) >> 5;
    int lane = threadIdx.x & 31;
    if (warp >= NB * NT) return;
    int b = warp >> 9, t = warp & 511;
    const float4* p = (const float4*)(x + (long)warp * NF);
    float4 v1 = p[lane];
    float4 v2 = p[lane + 32];
    bool nz = v1.x != 0.f || v1.y != 0.f || v1.z != 0.f || v1.w != 0.f ||
              v2.x != 0.f || v2.y != 0.f || v2.z != 0.f || v2.w != 0.f;
    unsigned m = __ballot_sync(0xffffffffu, nz);
    if (lane == 0 && m != 0u)
        atomicOr(&g_maskw[b * 16 + (t >> 5)], 1u << (t & 31));
}

// ---------------- prep: weights (block layout, swizzled, permuted) ----------------
// gate-aware column map: col n -> gate = 2*((n>>3)&1) + (n&1),
//                               unit = (n>>4)*4 + ((n>>1)&3)
__global__ void __launch_bounds__(256) prep_weights(
    const float* __restrict__ W, const float* __restrict__ U, const float* __restrict__ b) {
    long idx = (long)blockIdx.x * 256 + threadIdx.x; // 10*NG*128
    int hs = (int)(idx & 127);
    int n = (int)((idx >> 7) & (NG - 1));
    int kt = (int)(idx >> 19);
    int cc = (hs >> 4) ^ (n & 7);
    int hc = (cc << 4) | (hs & 15);
    int kl = (hc & ~15) | c_perm[hc & 15];
    int k = kt * BK + kl;
    int gate = 2 * ((n >> 3) & 1) + (n & 1);
    int j = (n >> 4) * 4 + ((n >> 1) & 3);
    float v = (k < NH) ? U[(long)k * NG + gate * NH + j]
                       : W[(long)(k - NH) * NG + gate * NH + j];
    g_MB[idx] = __float2half_rn(v);
    if (hs == 0 && kt == 0) g_bI[4 * j + gate] = b[gate * NH + j];
}

// ---------------- prep: x blocks + MLP combine + h0 zero + counter reset --------
__global__ void __launch_bounds__(256) prep_misc(
    const float* __restrict__ x, const float* __restrict__ W1) {
    const long N0 = (long)NT * 2 * NB * 8;  // x chunks of 16 halves
    const long N1 = (long)2048 * NH;
    const long N2 = (long)HSZ / 8;          // h0 zero in uint4 units
    long idx = (long)blockIdx.x * 256 + threadIdx.x;
    if (idx < N0) {
        int cs = (int)(idx & 7);
        int bb = (int)((idx >> 3) & 255);
        int kb = (int)((idx >> 11) & 1);
        int t = (int)(idx >> 12);
        int cc = cs ^ (bb & 7);
        const float* src = x + ((long)bb * NT + t) * NF + kb * 128 + cc * 16;
        float4 v0 = *(const float4*)(src);
        float4 v1 = *(const float4*)(src + 4);
        float4 v2 = *(const float4*)(src + 8);
        float4 v3 = *(const float4*)(src + 12);
        __half2 h[8];
        h[0] = __floats2half2_rn(v0.x, v0.y);
        h[1] = __floats2half2_rn(v2.x, v2.y);
        h[2] = __floats2half2_rn(v0.z, v0.w);
        h[3] = __floats2half2_rn(v2.z, v2.w);
        h[4] = __floats2half2_rn(v1.x, v1.y);
        h[5] = __floats2half2_rn(v3.x, v3.y);
        h[6] = __floats2half2_rn(v1.z, v1.w);
        h[7] = __floats2half2_rn(v3.z, v3.w);
        __half* dst = g_xB + ((((long)t * 2 + kb) * NB + bb) * 128 + cs * 16);
        *(uint4*)(dst) = *(uint4*)(h);
        *(uint4*)(dst + 8) = *(uint4*)(h + 4);
    } else if (idx < N0 + N1) {
        long r = idx - N0;
        int k = (int)(r >> 10), m = (int)(r & (NH - 1));
        float v = (k < NH) ? (W1[(long)k * NH + m] + W1[(long)(k + NH) * NH + m])
                           : W1[(long)(k + NH) * NH + m];
        g_MLP[r] = v;
    } else if (idx < N0 + N1 + N2) {
        ((uint4*)g_h)[idx - N0 - N1] = make_uint4(0, 0, 0, 0);
    } else if (idx < N0 + N1 + N2 + 16) {
        g_hcnt[idx - N0 - N1 - N2] = 0;
    }
}

// ---------------- persistent LSTM recurrence ----------------
__global__ void __launch_bounds__(256) lstm_persistent() {
    extern __shared__ __align__(128) char dsm[];
    __half* sh = (__half*)dsm;
    __shared__ __align__(8) unsigned long long s_mbar[NST];

    const int tid = threadIdx.x;
    const int lane = tid & 31;
    const int w = tid >> 5;
    const int wm = w & 1;
    const int wn = w >> 1;
    const int bn = blockIdx.x * BN;
    const int bm = blockIdx.y * BM;
    const int g = lane >> 2;
    const int c = lane & 3;
    const int c4 = 4 * c;
    const int kb_own = bn >> 9;     // the single h block this CTA writes

    const unsigned smb = smem_u32(sh);
    const unsigned mbb = smem_u32(s_mbar);

    if (tid == 0)
        for (int s = 0; s < NST; ++s) mbar_init(mbb + 8 * s, 1);
    __syncthreads();

    // fragment identities. This thread owns units u0, u0+4 for rows rbase+8*ri.
    const int rbase = bm + wm * 32 + g;
    const int u0 = ((bn + wn * 32) >> 4) * 4 + c;
    int hpos[2][4];
    float4 b4[2];
#pragma unroll
    for (int pp = 0; pp < 2; ++pp) {
        int u = u0 + 4 * pp;
        int q = (u & ~15) | c_pinv[u & 15];
        int kb = q >> 7, hc = q & 127;
#pragma unroll
        for (int ri = 0; ri < 4; ++ri) {
            int row = rbase + 8 * ri;
            hpos[pp][ri] = ((kb * NB + row) << 7) + (((hc >> 4) ^ (row & 7)) << 4)
                           + (hc & 15);
        }
        b4[pp] = *(const float4*)(g_bI + 4 * u);
    }
    float cst[8], hst[8];
#pragma unroll
    for (int i = 0; i < 8; ++i) { cst[i] = 0.0f; hst[i] = 0.0f; }

    int ph[NST] = {0, 0, 0, 0};
    unsigned mw[4] = {0, 0, 0, 0};

    // process order p: 0->kt8, 1->kt9 (x blocks), 2..9 -> kt0..kt7 (h blocks)
    auto bulkA_fill = [&](int kt, int s, const __half* hsrc, int t) {
        const __half* asrc = (kt < 8)
            ? (hsrc + ((long)kt * NB + bm) * BK)
            : (g_xB + (((long)t * 2 + (kt - 8)) * NB + bm) * BK);
        bulk_g2s(smb + s * ST_BY, asrc, A_BY, mbb + 8 * s);
    };
    auto bulkB_fill = [&](int kt, int s) {
        bulk_g2s(smb + s * ST_BY + A_BY, g_MB + ((long)kt * NG + bn) * BK, B_BY, mbb + 8 * s);
    };
    auto fill_p = [&](int p, int t, const __half* hsrc, int srcbuf, unsigned target) {
        const int kt = (p < 2) ? 8 + p : p - 2;
        const int s = (2 * t + p) & 3;
        mbar_expect_tx(mbb + 8 * s, (unsigned)ST_BY);
        bulkB_fill(kt, s);
        if (kt < 8 && t > 0) wait_cnt(&g_hcnt[srcbuf * 8 + kt], target);
        bulkA_fill(kt, s, hsrc, t);
    };

    // prologue: fills p=0,1 of t=0 (x blocks; stages 0,1; no gating)
    if (tid == 0) {
        mbar_expect_tx(mbb + 0, (unsigned)ST_BY);
        bulkB_fill(8, 0);
        bulkA_fill(8, 0, g_h, 0);
        mbar_expect_tx(mbb + 8, (unsigned)ST_BY);
        bulkB_fill(9, 1);
        bulkA_fill(9, 1, g_h, 0);
    }

    for (int t = 0; t < NT; ++t) {
        const int srcbuf = t & 1;
        const __half* __restrict__ hsrc = g_h + srcbuf * HSZ;
        __half* __restrict__ hdst = g_h + (srcbuf ^ 1) * HSZ;
        const unsigned target = 16u * (unsigned)((t + 1) >> 1);
        const int t2 = 2 * t;

        if ((t & 31) == 0) {
#pragma unroll
            for (int ri = 0; ri < 4; ++ri)
                mw[ri] = g_maskw[(rbase + 8 * ri) * 16 + (t >> 5)];
        }

        float acc[2][4][4];
#pragma unroll
        for (int i = 0; i < 2; ++i)
#pragma unroll
            for (int j = 0; j < 4; ++j)
#pragma unroll
                for (int k = 0; k < 4; ++k) acc[i][j][k] = 0.0f;

        for (int p = 0; p < NKT; ++p) {
            const int s = (t2 + p) & 3;
            if ((p & 1) == 0) {
                if (w == 0) mbar_wait(mbb + 8 * s, (unsigned)ph[s]);
                __syncthreads();
                if (tid == 0) {
                    if (p == 0 && t > 0) {  // deferred publish of step t-1's h
                        __threadfence();
                        atomicAdd(&g_hcnt[srcbuf * 8 + kb_own], 1u);
                    }
                    if (p < 8) {
                        fill_p(p + 2, t, hsrc, srcbuf, target);
                        fill_p(p + 3, t, hsrc, srcbuf, target);
                    } else if (t + 1 < NT) {
                        // p == 8: next step's x-block fills (ungated)
                        const int sA = (t2 + 2) & 3, sB = (t2 + 3) & 3;
                        mbar_expect_tx(mbb + 8 * sA, (unsigned)ST_BY);
                        bulkB_fill(8, sA);
                        bulkA_fill(8, sA, hsrc, t + 1);
                        mbar_expect_tx(mbb + 8 * sB, (unsigned)ST_BY);
                        bulkB_fill(9, sB);
                        bulkA_fill(9, sB, hsrc, t + 1);
                    }
                }
            } else {
                mbar_wait(mbb + 8 * s, (unsigned)ph[s]);
            }
            ph[s] ^= 1;

            const __half* Ab = sh + s * ST_H;
            const __half* arow = Ab + (wm * 32 + g) * BK;
            const __half* brow = Ab + A_H + (wn * 32 + g) * BK;

            // double-buffered fragment pipeline over the 8 chunks
            uint2 fA[2][4], fB[2][4];
            {
                const int o = (g << 4) + c4;
                fA[0][0] = *(const uint2*)(arow + o);
                fA[0][1] = *(const uint2*)(arow + 1024 + o);
                fA[0][2] = *(const uint2*)(arow + 2048 + o);
                fA[0][3] = *(const uint2*)(arow + 3072 + o);
                fB[0][0] = *(const uint2*)(brow + o);
                fB[0][1] = *(const uint2*)(brow + 1024 + o);
                fB[0][2] = *(const uint2*)(brow + 2048 + o);
                fB[0][3] = *(const uint2*)(brow + 3072 + o);
            }
#pragma unroll
            for (int ch = 0; ch < 8; ++ch) {
                const int cb = ch & 1;
                if (ch < 7) {
                    const int o = (((ch + 1) ^ g) << 4) + c4;
                    uint2* a = fA[cb ^ 1];
                    uint2* b = fB[cb ^ 1];
                    a[0] = *(const uint2*)(arow + o);
                    a[1] = *(const uint2*)(arow + 1024 + o);
                    a[2] = *(const uint2*)(arow + 2048 + o);
                    a[3] = *(const uint2*)(arow + 3072 + o);
                    b[0] = *(const uint2*)(brow + o);
                    b[1] = *(const uint2*)(brow + 1024 + o);
                    b[2] = *(const uint2*)(brow + 2048 + o);
                    b[3] = *(const uint2*)(brow + 3072 + o);
                }
                const uint2* a = fA[cb];
                const uint2* b = fB[cb];
                mma16(acc[0][0], a[0].x, a[1].x, a[0].y, a[1].y, b[0].x, b[0].y);
                mma16(acc[0][1], a[0].x, a[1].x, a[0].y, a[1].y, b[1].x, b[1].y);
                mma16(acc[0][2], a[0].x, a[1].x, a[0].y, a[1].y, b[2].x, b[2].y);
                mma16(acc[0][3], a[0].x, a[1].x, a[0].y, a[1].y, b[3].x, b[3].y);
                mma16(acc[1][0], a[2].x, a[3].x, a[2].y, a[3].y, b[0].x, b[0].y);
                mma16(acc[1][1], a[2].x, a[3].x, a[2].y, a[3].y, b[1].x, b[1].y);
                mma16(acc[1][2], a[2].x, a[3].x, a[2].y, a[3].y, b[2].x, b[2].y);
                mma16(acc[1][3], a[2].x, a[3].x, a[2].y, a[3].y, b[3].x, b[3].y);
            }
        }

        // shuffle-free epilogue: acc[mt][2pp] = gates i,f; acc[mt][2pp+1] = g,o
        // [0],[1] -> row rbase+16*mt; [2],[3] -> row +8.
#pragma unroll
        for (int mt = 0; mt < 2; ++mt)
#pragma unroll
            for (int pp = 0; pp < 2; ++pp) {
                const float* f0 = acc[mt][2 * pp];
                const float* f1 = acc[mt][2 * pp + 1];
                const float4 bb = b4[pp];
#pragma unroll
                for (int rr = 0; rr < 2; ++rr) {
                    const int ri = 2 * mt + rr;
                    const int i = pp * 4 + ri;
                    float zi = f0[2 * rr]     + bb.x;
                    float zf = f0[2 * rr + 1] + bb.y;
                    float zg = f1[2 * rr]     + bb.z;
                    float zo = f1[2 * rr + 1] + bb.w;
                    float iv = sigmf(zi), fv = sigmf(zf);
                    float gv = tanhfa(zg), ov = sigmf(zo);
                    float cn = fv * cst[i] + iv * gv;
                    float hn = ov * tanhfa(cn);
                    if (!((mw[ri] >> (t & 31)) & 1u)) { cn = cst[i]; hn = hst[i]; }
                    cst[i] = cn;
                    hst[i] = hn;
                    hdst[hpos[pp][ri]] = __float2half_rn(hn);
                }
            }
        // no trailing sync: publish deferred to next step's p=0 sync
    }

    // final c (fp32) for the MLP head
#pragma unroll
    for (int pp = 0; pp < 2; ++pp)
#pragma unroll
        for (int ri = 0; ri < 4; ++ri)
            g_cf[(long)(rbase + 8 * ri) * NH + (u0 + 4 * pp)] = cst[pp * 4 + ri];
    __syncthreads();
    if (tid == 0)
        for (int s = 0; s < NST; ++s) mbar_inval(mbb + 8 * s);
}

// un-permute/un-swizzle final h (buffer 0 after 512 steps) to fp32
__global__ void __launch_bounds__(256) unperm_h() {
    int idx = blockIdx.x * 256 + threadIdx.x; // NB*NH
    int b = idx >> 10, j = idx & 1023;
    int q = (j & ~15) | c_pinv[j & 15];
    int kb = q >> 7, hc = q & 127;
    long off = (((long)kb * NB + b) << 7) + (((hc >> 4) ^ (b & 7)) << 4) + (hc & 15);
    g_hf[idx] = __half2float(g_h[off]);
}

// ---------------- MLP head ----------------
__global__ void __launch_bounds__(256) mlp1_kernel(const float* __restrict__ b1) {
    __shared__ float a_s[64 * 20];
    __shared__ float b_s[16 * 68];
    int tid = threadIdx.x;
    int bn = blockIdx.x * 64, bm = blockIdx.y * 64;
    int ty = tid >> 4, tx = tid & 15;
    float acc[4][4];
#pragma unroll
    for (int i = 0; i < 4; ++i)
#pragma unroll
        for (int j = 0; j < 4; ++j) acc[i][j] = 0.0f;

    for (int kt = 0; kt < 128; ++kt) {
        int k0 = kt * 16;
        {
            int m = tid >> 2, kq = tid & 3;
            int k = k0 + 4 * kq;
            const float* src = (k < NH) ? (g_hf + (long)(bm + m) * NH + k)
                                        : (g_cf + (long)(bm + m) * NH + (k - NH));
            *(float4*)(a_s + m * 20 + 4 * kq) = *(const float4*)src;
        }
        {
            int kr = tid >> 4, cq = tid & 15;
            *(float4*)(b_s + kr * 68 + 4 * cq) =
                *(const float4*)(g_MLP + (long)(k0 + kr) * NH + bn + 4 * cq);
        }
        __syncthreads();
#pragma unroll
        for (int k = 0; k < 16; ++k) {
            float ar[4], br[4];
#pragma unroll
            for (int i = 0; i < 4; ++i) {
                ar[i] = a_s[(4 * ty + i) * 20 + k];
                br[i] = b_s[k * 68 + 4 * tx + i];
            }
#pragma unroll
            for (int i = 0; i < 4; ++i)
#pragma unroll
                for (int j = 0; j < 4; ++j) acc[i][j] += ar[i] * br[j];
        }
        __syncthreads();
    }
#pragma unroll
    for (int i = 0; i < 4; ++i)
#pragma unroll
        for (int j = 0; j < 4; ++j) {
            float v = acc[i][j] + b1[bn + 4 * tx + j];
            v = v > 0.0f ? v : 0.2f * v;
            g_y1[(long)(bm + 4 * ty + i) * NH + bn + 4 * tx + j] = v;
        }
}

__global__ void __launch_bounds__(64) mlp2_kernel(
    const float* __restrict__ W2, const float* __restrict__ b2, float* __restrict__ out) {
    __shared__ float row[NH];
    int bg = blockIdx.x;
    int o = threadIdx.x;
    for (int i = o; i < NH; i += 64) row[i] = g_y1[(long)bg * NH + i];
    __syncthreads();
    float acc = b2[o];
#pragma unroll 8
    for (int k = 0; k < NH; ++k) acc += row[k] * W2[(long)k * NOUT + o];
    out[(long)bg * NOUT + o] = acc;
}

// ---------------- launch ----------------
extern "C" void kernel_launch(void* const* d_in, const int* in_sizes, int n_in,
                              void* d_out, int out_size) {
    const float* x  = (const float*)d_in[0];
    const float* W  = (const float*)d_in[1];
    const float* U  = (const float*)d_in[2];
    const float* b  = (const float*)d_in[3];
    const float* W1 = (const float*)d_in[4];
    const float* b1 = (const float*)d_in[5];
    const float* W2 = (const float*)d_in[6];
    const float* b2 = (const float*)d_in[7];
    float* out = (float*)d_out;

    cudaFuncSetAttribute(lstm_persistent,
                         cudaFuncAttributeMaxDynamicSharedMemorySize, SMEM_BYTES);

    const long WN = (long)10 * NG * 128;
    const long MN = (long)NT * 2 * NB * 8 + (long)2048 * NH + (long)HSZ / 8 + 16;

    // lstm_persistent is the 4th launch (ncu profiles launch index 3)
    mask_kernel<<<(NB * NT * 32) / 256, 256>>>(x);
    prep_weights<<<(int)(WN / 256), 256>>>(W, U, b);
    prep_misc<<<(int)((MN + 255) / 256), 256>>>(x, W1);
    lstm_persistent<<<dim3(NG / BN, NB / BM), 256, SMEM_BYTES>>>();
    unperm_h<<<(NB * NH) / 256, 256>>>();
    mlp1_kernel<<<dim3(NH / 64, NB / 64), 256>>>(b1);
    mlp2_kernel<<<NB, 64>>>(W2, b2, out);
}